// round 16
// baseline (speedup 1.0000x reference)
#include <cuda_runtime.h>
#include <cuda_bf16.h>
#include <cuda_fp16.h>
#include <cstdint>

// Problem constants
#define HH   64
#define WW   128
#define CC   256
#define NPIX (HH * WW)          // 8192
#define NH   8
#define HD   32
#define C3   (3 * CC)           // 768
#define KK   7

// ---------------------------------------------------------------------------
// Scratch (device globals; no allocation allowed)
// ---------------------------------------------------------------------------
__device__ __align__(16) float         g_q[NPIX * CC];          // q fp32
__device__ __align__(16) __half        g_kv[NPIX * 2 * CC];     // k|v fp16 (512/pix)
__device__ __align__(16) __nv_bfloat16 g_xh[NPIX * CC];
__device__ __align__(16) __nv_bfloat16 g_xl[NPIX * CC];
__device__ __align__(16) __nv_bfloat16 g_wqkvT_h[C3 * CC];
__device__ __align__(16) __nv_bfloat16 g_wqkvT_l[C3 * CC];
__device__ __align__(16) __nv_bfloat16 g_wprojT_h[CC * CC];
__device__ __align__(16) __nv_bfloat16 g_wprojT_l[CC * CC];
__device__ __align__(16) __nv_bfloat16 g_atth[NPIX * CC];
__device__ __align__(16) __nv_bfloat16 g_attl[NPIX * CC];

// ---------------------------------------------------------------------------
// PTX helpers (baseline ISA: mma.sync / ldmatrix / cp.async)
// ---------------------------------------------------------------------------
__device__ __forceinline__ uint32_t smem_u32(const void* p) {
    uint32_t a;
    asm("{ .reg .u64 t; cvta.to.shared.u64 t, %1; cvt.u32.u64 %0, t; }"
        : "=r"(a) : "l"(p));
    return a;
}

__device__ __forceinline__ void cp_async16(uint32_t saddr, const void* gptr) {
    asm volatile("cp.async.cg.shared.global [%0], [%1], 16;"
                 :: "r"(saddr), "l"(gptr) : "memory");
}

__device__ __forceinline__ void ldsm_x4(uint32_t* r, uint32_t addr) {
    asm volatile("ldmatrix.sync.aligned.m8n8.x4.shared.b16 {%0,%1,%2,%3}, [%4];"
                 : "=r"(r[0]), "=r"(r[1]), "=r"(r[2]), "=r"(r[3]) : "r"(addr));
}

__device__ __forceinline__ void mma_16816(float* c, const uint32_t* a,
                                          const uint32_t* b) {
    asm volatile(
        "mma.sync.aligned.m16n8k16.row.col.f32.bf16.bf16.f32 "
        "{%0,%1,%2,%3}, {%4,%5,%6,%7}, {%8,%9}, {%0,%1,%2,%3};"
        : "+f"(c[0]), "+f"(c[1]), "+f"(c[2]), "+f"(c[3])
        : "r"(a[0]), "r"(a[1]), "r"(a[2]), "r"(a[3]), "r"(b[0]), "r"(b[1]));
}

// SW64 swizzle for 64B rows: chunk bits [4:5] ^= row-pair bits [7:8]
__device__ __forceinline__ uint32_t sw64(uint32_t off) {
    return off ^ ((off >> 3) & 0x30);
}

// ---------------------------------------------------------------------------
// Fused prep: split x (hi/lo bf16, float4-vectorized) + transpose/split weights
// ---------------------------------------------------------------------------
#define PREP_XB  (NPIX * CC / 1024)           // 2048 (4 elems/thread)
#define PREP_QB  (CC * C3 / 256)              // 768
#define PREP_PB  (CC * CC / 256)              // 256

__global__ void prep_all(const float* __restrict__ x,
                         const float* __restrict__ wq,
                         const float* __restrict__ wp,
                         __nv_bfloat16* __restrict__ xh, __nv_bfloat16* __restrict__ xl,
                         __nv_bfloat16* __restrict__ qh, __nv_bfloat16* __restrict__ ql,
                         __nv_bfloat16* __restrict__ ph, __nv_bfloat16* __restrict__ pl)
{
    const int b = blockIdx.x;
    if (b < PREP_XB) {
        const int i4 = (b * 256 + threadIdx.x) * 4;
        const float4 v = *(const float4*)&x[i4];
        __nv_bfloat16 h[4], l[4];
        const float vv[4] = {v.x, v.y, v.z, v.w};
#pragma unroll
        for (int j = 0; j < 4; j++) {
            h[j] = __float2bfloat16(vv[j]);
            l[j] = __float2bfloat16(vv[j] - __bfloat162float(h[j]));
        }
        *(uint2*)&xh[i4] = *(const uint2*)h;
        *(uint2*)&xl[i4] = *(const uint2*)l;
    } else if (b < PREP_XB + PREP_QB) {
        const int i = (b - PREP_XB) * 256 + threadIdx.x;   // over C3*CC
        const int n = i / CC, k = i % CC;
        const float v = wq[(size_t)k * C3 + n];
        const __nv_bfloat16 hi = __float2bfloat16(v);
        qh[i] = hi;                                        // i == n*CC + k
        ql[i] = __float2bfloat16(v - __bfloat162float(hi));
    } else {
        const int i = (b - PREP_XB - PREP_QB) * 256 + threadIdx.x;  // CC*CC
        const int n = i / CC, k = i % CC;
        const float v = wp[(size_t)k * CC + n];
        const __nv_bfloat16 hi = __float2bfloat16(v);
        ph[i] = hi;
        pl[i] = __float2bfloat16(v - __bfloat162float(hi));
    }
}

// ---------------------------------------------------------------------------
// NARROW GEMM (proj): CTA 128x64, 4 warps (2Mx2N), warp tile 64x32.
// BKC=32, 64B rows + SW64. 3-term bf16 split.
// Epilogue: bx < nq -> fp32 (width 256); bx >= nq -> fp16 kv (width 512)
// ---------------------------------------------------------------------------
#define BKC 32
#define AB_BYTES (128 * 64)                  // 8192 per A buffer
#define BB_BYTES (64 * 64)                   // 4096 per B buffer
#define STG_BYTES (2 * AB_BYTES + 2 * BB_BYTES)  // 24576
#define GT_SMEM (2 * STG_BYTES)              // 49152

__global__ __launch_bounds__(128, 3)
void gemm_mma(const __nv_bfloat16* __restrict__ Ah, const __nv_bfloat16* __restrict__ Al,
              const __nv_bfloat16* __restrict__ Bh, const __nv_bfloat16* __restrict__ Bl,
              const float* __restrict__ bias,
              float* __restrict__ Cq, __half* __restrict__ Ckv,
              int nq, int K)
{
    extern __shared__ char smem[];
    const uint32_t sb = smem_u32(smem);
    const int tid  = threadIdx.x;
    const int wid  = tid >> 5;
    const int lane = tid & 31;
    const int warpM = wid & 1;
    const int warpN = wid >> 1;

    const size_t aBase = (size_t)blockIdx.y * 128 * K;
    const size_t bBase = (size_t)blockIdx.x * 64 * K;
    const int nch = K / BKC;

    auto issue_chunk = [&](int c) {
        const uint32_t st = sb + (uint32_t)(c & 1) * STG_BYTES;
        const int k0 = c * BKC;
#pragma unroll
        for (int i = 0; i < 4; i++) {
            const int idx = i * 128 + tid;
            const int r = idx >> 2, u = idx & 3;
            const uint32_t so = sw64((uint32_t)r * 64 + (uint32_t)u * 16);
            const size_t ga = aBase + (size_t)r * K + k0 + u * 8;
            cp_async16(st + so, Ah + ga);
            cp_async16(st + AB_BYTES + so, Al + ga);
        }
#pragma unroll
        for (int i = 0; i < 2; i++) {
            const int idx = i * 128 + tid;
            const int r = idx >> 2, u = idx & 3;
            const uint32_t so = sw64((uint32_t)r * 64 + (uint32_t)u * 16);
            const size_t gb = bBase + (size_t)r * K + k0 + u * 8;
            cp_async16(st + 2 * AB_BYTES + so, Bh + gb);
            cp_async16(st + 2 * AB_BYTES + BB_BYTES + so, Bl + gb);
        }
        asm volatile("cp.async.commit_group;" ::: "memory");
    };

    float acc[4][4][4];
#pragma unroll
    for (int i = 0; i < 4; i++)
#pragma unroll
        for (int j = 0; j < 4; j++)
#pragma unroll
            for (int t = 0; t < 4; t++) acc[i][j][t] = 0.0f;

    const uint32_t arow  = (uint32_t)(warpM * 64 + (lane & 15));
    const uint32_t acolL = (uint32_t)((lane >> 4) * 16);
    const uint32_t brow  = (uint32_t)(warpN * 32 + (lane & 7) + ((lane >> 4) << 3));
    const uint32_t bcolL = (uint32_t)(((lane >> 3) & 1) * 16);

    issue_chunk(0);

    for (int c = 0; c < nch; c++) {
        if (c + 1 < nch) {
            issue_chunk(c + 1);
            asm volatile("cp.async.wait_group 1;" ::: "memory");
        } else {
            asm volatile("cp.async.wait_group 0;" ::: "memory");
        }
        __syncthreads();

        const uint32_t st  = sb + (uint32_t)(c & 1) * STG_BYTES;
        const uint32_t sA0 = st;
        const uint32_t sA1 = st + AB_BYTES;
        const uint32_t sB0 = st + 2 * AB_BYTES;
        const uint32_t sB1 = st + 2 * AB_BYTES + BB_BYTES;

#pragma unroll
        for (int ks = 0; ks < 2; ks++) {
            const uint32_t kb = (uint32_t)ks * 32;

            uint32_t ah[4][4], al[4][4];
#pragma unroll
            for (int ma = 0; ma < 4; ma++) {
                const uint32_t off = sw64((arow + ma * 16) * 64 + kb + acolL);
                ldsm_x4(ah[ma], sA0 + off);
                ldsm_x4(al[ma], sA1 + off);
            }

            uint32_t bh[4][2], bl[4][2];
#pragma unroll
            for (int g = 0; g < 2; g++) {
                const uint32_t off = sw64((brow + g * 16) * 64 + kb + bcolL);
                uint32_t t0[4], t1[4];
                ldsm_x4(t0, sB0 + off);
                ldsm_x4(t1, sB1 + off);
                bh[2 * g][0] = t0[0]; bh[2 * g][1] = t0[1];
                bh[2 * g + 1][0] = t0[2]; bh[2 * g + 1][1] = t0[3];
                bl[2 * g][0] = t1[0]; bl[2 * g][1] = t1[1];
                bl[2 * g + 1][0] = t1[2]; bl[2 * g + 1][1] = t1[3];
            }

#pragma unroll
            for (int ma = 0; ma < 4; ma++)
#pragma unroll
                for (int na = 0; na < 4; na++) {
                    mma_16816(acc[ma][na], ah[ma], bh[na]);
                    mma_16816(acc[ma][na], ah[ma], bl[na]);
                    mma_16816(acc[ma][na], al[ma], bh[na]);
                }
        }
        __syncthreads();
    }

    const int bx = blockIdx.x;
    const int row0 = blockIdx.y * 128 + warpM * 64 + (lane >> 2);
    const int lcol = warpN * 32 + (lane & 3) * 2;
#pragma unroll
    for (int na = 0; na < 4; na++) {
        const int wc = lcol + na * 8;
        const int gcol = bx * 64 + wc;
        const float2 b2 = *(const float2*)&bias[gcol];
        if (bx < nq) {
#pragma unroll
            for (int ma = 0; ma < 4; ma++) {
                const int r = row0 + ma * 16;
                float2 o0, o1;
                o0.x = acc[ma][na][0] + b2.x;
                o0.y = acc[ma][na][1] + b2.y;
                o1.x = acc[ma][na][2] + b2.x;
                o1.y = acc[ma][na][3] + b2.y;
                *(float2*)&Cq[(size_t)r * 256 + gcol]       = o0;
                *(float2*)&Cq[(size_t)(r + 8) * 256 + gcol] = o1;
            }
        } else {
            const int kvc = (bx - nq) * 64 + wc;
#pragma unroll
            for (int ma = 0; ma < 4; ma++) {
                const int r = row0 + ma * 16;
                __half2 o0 = __floats2half2_rn(acc[ma][na][0] + b2.x,
                                               acc[ma][na][1] + b2.y);
                __half2 o1 = __floats2half2_rn(acc[ma][na][2] + b2.x,
                                               acc[ma][na][3] + b2.y);
                *(__half2*)&Ckv[(size_t)r * 512 + kvc]       = o0;
                *(__half2*)&Ckv[(size_t)(r + 8) * 512 + kvc] = o1;
            }
        }
    }
}

// ---------------------------------------------------------------------------
// WIDE GEMM (QKV): CTA 128x128, 128 threads, 4 warps (2Mx2N), warp 64x64.
// 85 B/MMA through the crossbar (vs 128 narrow) -> ceiling ~58%.
// BKC=32, SW64; stage 32KB, 2 stages = 64KB -> 2 CTA/SM (8 warps).
// Epilogue: 128-wide tiles; bx < nq -> fp32 q; bx >= nq -> fp16 kv.
// ---------------------------------------------------------------------------
#define WAB (128 * 64)                        // 8192 per buffer (A or B, hi or lo)
#define WSTG (4 * WAB)                        // 32768
#define GW_SMEM (2 * WSTG)                    // 65536

__global__ __launch_bounds__(128, 2)
void gemm_mma_wide(const __nv_bfloat16* __restrict__ Ah, const __nv_bfloat16* __restrict__ Al,
                   const __nv_bfloat16* __restrict__ Bh, const __nv_bfloat16* __restrict__ Bl,
                   const float* __restrict__ bias,
                   float* __restrict__ Cq, __half* __restrict__ Ckv,
                   int nq, int K)
{
    extern __shared__ char smem[];
    const uint32_t sb = smem_u32(smem);
    const int tid  = threadIdx.x;
    const int wid  = tid >> 5;
    const int lane = tid & 31;
    const int warpM = wid & 1;               // 64 rows each
    const int warpN = wid >> 1;              // 64 cols each

    const size_t aBase = (size_t)blockIdx.y * 128 * K;
    const size_t bBase = (size_t)blockIdx.x * 128 * K;
    const int nch = K / BKC;                 // BKC = 32

    auto issue_chunk = [&](int c) {
        const uint32_t st = sb + (uint32_t)(c & 1) * WSTG;
        const int k0 = c * BKC;
        // A and B: each 128 rows x 4 16B-units = 512 transfers -> 4 iters
#pragma unroll
        for (int i = 0; i < 4; i++) {
            const int idx = i * 128 + tid;
            const int r = idx >> 2, u = idx & 3;
            const uint32_t so = sw64((uint32_t)r * 64 + (uint32_t)u * 16);
            const size_t ga = aBase + (size_t)r * K + k0 + u * 8;
            const size_t gb = bBase + (size_t)r * K + k0 + u * 8;
            cp_async16(st + so,           Ah + ga);
            cp_async16(st + WAB + so,     Al + ga);
            cp_async16(st + 2 * WAB + so, Bh + gb);
            cp_async16(st + 3 * WAB + so, Bl + gb);
        }
        asm volatile("cp.async.commit_group;" ::: "memory");
    };

    float acc[4][8][4];
#pragma unroll
    for (int i = 0; i < 4; i++)
#pragma unroll
        for (int j = 0; j < 8; j++)
#pragma unroll
            for (int t = 0; t < 4; t++) acc[i][j][t] = 0.0f;

    const uint32_t arow  = (uint32_t)(warpM * 64 + (lane & 15));
    const uint32_t acolL = (uint32_t)((lane >> 4) * 16);
    const uint32_t brow  = (uint32_t)(warpN * 64 + (lane & 7) + ((lane >> 4) << 3));
    const uint32_t bcolL = (uint32_t)(((lane >> 3) & 1) * 16);

    issue_chunk(0);

    for (int c = 0; c < nch; c++) {
        if (c + 1 < nch) {
            issue_chunk(c + 1);
            asm volatile("cp.async.wait_group 1;" ::: "memory");
        } else {
            asm volatile("cp.async.wait_group 0;" ::: "memory");
        }
        __syncthreads();

        const uint32_t st  = sb + (uint32_t)(c & 1) * WSTG;
        const uint32_t sA0 = st;
        const uint32_t sA1 = st + WAB;
        const uint32_t sB0 = st + 2 * WAB;
        const uint32_t sB1 = st + 3 * WAB;

#pragma unroll
        for (int ks = 0; ks < 2; ks++) {
            const uint32_t kb = (uint32_t)ks * 32;

            uint32_t ah[4][4], al[4][4];
#pragma unroll
            for (int ma = 0; ma < 4; ma++) {
                const uint32_t off = sw64((arow + ma * 16) * 64 + kb + acolL);
                ldsm_x4(ah[ma], sA0 + off);
                ldsm_x4(al[ma], sA1 + off);
            }

            uint32_t bh[8][2], bl[8][2];
#pragma unroll
            for (int g = 0; g < 4; g++) {
                const uint32_t off = sw64((brow + g * 16) * 64 + kb + bcolL);
                uint32_t t0[4], t1[4];
                ldsm_x4(t0, sB0 + off);
                ldsm_x4(t1, sB1 + off);
                bh[2 * g][0] = t0[0]; bh[2 * g][1] = t0[1];
                bh[2 * g + 1][0] = t0[2]; bh[2 * g + 1][1] = t0[3];
                bl[2 * g][0] = t1[0]; bl[2 * g][1] = t1[1];
                bl[2 * g + 1][0] = t1[2]; bl[2 * g + 1][1] = t1[3];
            }

#pragma unroll
            for (int ma = 0; ma < 4; ma++)
#pragma unroll
                for (int na = 0; na < 8; na++) {
                    mma_16816(acc[ma][na], ah[ma], bh[na]);
                    mma_16816(acc[ma][na], ah[ma], bl[na]);
                    mma_16816(acc[ma][na], al[ma], bh[na]);
                }
        }
        __syncthreads();
    }

    // ---- epilogue (128-wide tiles) ----
    const int bx = blockIdx.x;
    const int row0 = blockIdx.y * 128 + warpM * 64 + (lane >> 2);
    const int lcol = warpN * 64 + (lane & 3) * 2;
#pragma unroll
    for (int na = 0; na < 8; na++) {
        const int wc = lcol + na * 8;
        const int gcol = bx * 128 + wc;
        const float2 b2 = *(const float2*)&bias[gcol];
        if (bx < nq) {
#pragma unroll
            for (int ma = 0; ma < 4; ma++) {
                const int r = row0 + ma * 16;
                float2 o0, o1;
                o0.x = acc[ma][na][0] + b2.x;
                o0.y = acc[ma][na][1] + b2.y;
                o1.x = acc[ma][na][2] + b2.x;
                o1.y = acc[ma][na][3] + b2.y;
                *(float2*)&Cq[(size_t)r * 256 + gcol]       = o0;
                *(float2*)&Cq[(size_t)(r + 8) * 256 + gcol] = o1;
            }
        } else {
            const int kvc = (bx - nq) * 128 + wc;
#pragma unroll
            for (int ma = 0; ma < 4; ma++) {
                const int r = row0 + ma * 16;
                __half2 o0 = __floats2half2_rn(acc[ma][na][0] + b2.x,
                                               acc[ma][na][1] + b2.y);
                __half2 o1 = __floats2half2_rn(acc[ma][na][2] + b2.x,
                                               acc[ma][na][3] + b2.y);
                *(__half2*)&Ckv[(size_t)r * 512 + kvc]       = o0;
                *(__half2*)&Ckv[(size_t)(r + 8) * 512 + kvc] = o1;
            }
        }
    }
}

// ---------------------------------------------------------------------------
// 2D neighborhood attention (7x7): one pixel per thread, single fused pass.
// (R13 config: 16x16 tile, 80B pixel stride, conflict-free, bounded-score exp)
// ---------------------------------------------------------------------------
#define ATS   16
#define AWIN  22
#define APS   80
#define AKV   (AWIN * AWIN * APS)             // 38720 per buffer
#define AT_SMEM (2 * AKV)                     // 77440

__global__ __launch_bounds__(256, 2)
void na_attn(const float* __restrict__ qbuf, const __half* __restrict__ kvbuf,
             __nv_bfloat16* __restrict__ outh, __nv_bfloat16* __restrict__ outl)
{
    extern __shared__ char smn[];
    char* sK = smn;
    char* sV = smn + AKV;

    const int c0   = blockIdx.x * ATS;
    const int r0   = blockIdx.y * ATS;
    const int head = blockIdx.z;

    const int rlo = max(r0 - 3, 0);
    const int rhi = min(r0 + ATS + 2, HH - 1);
    const int nr  = rhi - rlo + 1;
    const int clo = max(c0 - 3, 0);
    const int chi = min(c0 + ATS + 2, WW - 1);
    const int nc  = chi - clo + 1;
    const int npx = nr * nc;

    const int tid = threadIdx.x;

    for (int t = tid; t < npx * 4; t += 256) {
        const int p = t >> 2, u = t & 3;
        const int gy = rlo + p / nc;
        const int gx = clo + p % nc;
        const __half* base = kvbuf + (size_t)(gy * WW + gx) * 512 + head * HD;
        *(uint4*)(sK + p * APS + u * 16) = *(const uint4*)(base + u * 8);
        *(uint4*)(sV + p * APS + u * 16) = *(const uint4*)(base + 256 + u * 8);
    }
    __syncthreads();

    const int ly = tid >> 4, lx = tid & 15;
    const int gy = r0 + ly, gx = c0 + lx;
    const size_t pix = (size_t)(gy * WW + gx);
    const float scale = 0.17677669529663687f;

    __half2 qh[16];
    {
        const float4* qp = (const float4*)&qbuf[pix * CC + head * HD];
#pragma unroll
        for (int i = 0; i < 8; i++) {
            const float4 v = qp[i];
            qh[2 * i + 0] = __floats2half2_rn(v.x * scale, v.y * scale);
            qh[2 * i + 1] = __floats2half2_rn(v.z * scale, v.w * scale);
        }
    }

    const int sy = min(max(gy - 3, 0), HH - KK) - rlo;
    const int sx = min(max(gx - 3, 0), WW - KK) - clo;
    const int pbase = sy * nc + sx;

    float acc[32];
#pragma unroll
    for (int i = 0; i < 32; i++) acc[i] = 0.0f;
    float l = 0.0f;

    const __half2 z2 = __float2half2_rn(0.0f);

#pragma unroll 1
    for (int p = 0; p < KK; p++) {
        const char* krow = sK + (size_t)(pbase + p * nc) * APS;
        const char* vrow = sV + (size_t)(pbase + p * nc) * APS;
#pragma unroll
        for (int qq = 0; qq < KK; qq++) {
            const uint4* kp = (const uint4*)(krow + qq * APS);
            __half2 s2a = z2, s2b = z2;
#pragma unroll
            for (int i = 0; i < 4; i++) {
                const uint4 u = kp[i];
                s2a = __hfma2(qh[4 * i + 0], *(const __half2*)&u.x, s2a);
                s2b = __hfma2(qh[4 * i + 1], *(const __half2*)&u.y, s2b);
                s2a = __hfma2(qh[4 * i + 2], *(const __half2*)&u.z, s2a);
                s2b = __hfma2(qh[4 * i + 3], *(const __half2*)&u.w, s2b);
            }
            const float2 fa = __half22float2(s2a);
            const float2 fb = __half22float2(s2b);
            const float s = (fa.x + fa.y) + (fb.x + fb.y);

            const float e = __expf(s);
            l += e;

            const uint4* vp = (const uint4*)(vrow + qq * APS);
#pragma unroll
            for (int i = 0; i < 4; i++) {
                const uint4 u = vp[i];
                const float2 f0 = __half22float2(*(const __half2*)&u.x);
                const float2 f1 = __half22float2(*(const __half2*)&u.y);
                const float2 f2 = __half22float2(*(const __half2*)&u.z);
                const float2 f3 = __half22float2(*(const __half2*)&u.w);
                acc[8 * i + 0] = fmaf(e, f0.x, acc[8 * i + 0]);
                acc[8 * i + 1] = fmaf(e, f0.y, acc[8 * i + 1]);
                acc[8 * i + 2] = fmaf(e, f1.x, acc[8 * i + 2]);
                acc[8 * i + 3] = fmaf(e, f1.y, acc[8 * i + 3]);
                acc[8 * i + 4] = fmaf(e, f2.x, acc[8 * i + 4]);
                acc[8 * i + 5] = fmaf(e, f2.y, acc[8 * i + 5]);
                acc[8 * i + 6] = fmaf(e, f3.x, acc[8 * i + 6]);
                acc[8 * i + 7] = fmaf(e, f3.y, acc[8 * i + 7]);
            }
        }
    }

    const float inv = 1.0f / l;
    const size_t idx = pix * CC + head * HD;
#pragma unroll
    for (int i = 0; i < 8; i++) {
        __nv_bfloat16 h[4], lo[4];
#pragma unroll
        for (int j = 0; j < 4; j++) {
            const float v = acc[4 * i + j] * inv;
            h[j]  = __float2bfloat16(v);
            lo[j] = __float2bfloat16(v - __bfloat162float(h[j]));
        }
        *(uint2*)&outh[idx + 4 * i] = *(const uint2*)h;
        *(uint2*)&outl[idx + 4 * i] = *(const uint2*)lo;
    }
}

// ---------------------------------------------------------------------------
// kernel_launch
// ---------------------------------------------------------------------------
extern "C" void kernel_launch(void* const* d_in, const int* in_sizes, int n_in,
                              void* d_out, int out_size)
{
    const float* x      = (const float*)d_in[0];
    const float* w_qkv  = (const float*)d_in[1];
    const float* b_qkv  = (const float*)d_in[2];
    const float* w_proj = (const float*)d_in[3];
    const float* b_proj = (const float*)d_in[4];
    float* out = (float*)d_out;

    float *qb;
    __half *kvb;
    __nv_bfloat16 *xh, *xl, *wqh, *wql, *wph, *wpl, *ath, *atl;
    cudaGetSymbolAddress((void**)&qb,  g_q);
    cudaGetSymbolAddress((void**)&kvb, g_kv);
    cudaGetSymbolAddress((void**)&xh,  g_xh);
    cudaGetSymbolAddress((void**)&xl,  g_xl);
    cudaGetSymbolAddress((void**)&wqh, g_wqkvT_h);
    cudaGetSymbolAddress((void**)&wql, g_wqkvT_l);
    cudaGetSymbolAddress((void**)&wph, g_wprojT_h);
    cudaGetSymbolAddress((void**)&wpl, g_wprojT_l);
    cudaGetSymbolAddress((void**)&ath, g_atth);
    cudaGetSymbolAddress((void**)&atl, g_attl);

    cudaFuncSetAttribute(gemm_mma, cudaFuncAttributeMaxDynamicSharedMemorySize,
                         GT_SMEM);
    cudaFuncSetAttribute(gemm_mma_wide, cudaFuncAttributeMaxDynamicSharedMemorySize,
                         GW_SMEM);
    cudaFuncSetAttribute(na_attn, cudaFuncAttributeMaxDynamicSharedMemorySize,
                         AT_SMEM);

    // 0) Fused prep: split x (vectorized) + transpose/split both weights
    prep_all<<<PREP_XB + PREP_QB + PREP_PB, 256>>>(x, w_qkv, w_proj,
                                                   xh, xl, wqh, wql, wph, wpl);

    // 1) QKV projection (wide tiles): [8192,256] @ [256,768] + b
    //    128-col tiles 0-1 -> q fp32; tiles 2-5 -> k|v fp16 into kv buffer
    {
        dim3 grid(C3 / 128, NPIX / 128);
        gemm_mma_wide<<<grid, 128, GW_SMEM>>>(xh, xl, wqh, wql, b_qkv,
                                              qb, kvb, /*nq=*/2, CC);
    }

    // 2) Neighborhood attention (one pixel/thread, fused pass; bf16 hi/lo out)
    {
        dim3 grid(WW / ATS, HH / ATS, NH);
        na_attn<<<grid, 256, AT_SMEM>>>(qb, kvb, ath, atl);
    }

    // 3) Output projection (narrow tiles): [8192,256] @ [256,256] + b
    {
        dim3 grid(CC / 64, NPIX / 128);
        gemm_mma<<<grid, 128, GT_SMEM>>>(ath, atl, wph, wpl, b_proj,
                                         out, (__half*)nullptr, /*nq=*/4, CC);
    }
}

// round 17
// speedup vs baseline: 1.0740x; 1.0740x over previous
#include <cuda_runtime.h>
#include <cuda_bf16.h>
#include <cuda_fp16.h>
#include <cstdint>

// Problem constants
#define HH   64
#define WW   128
#define CC   256
#define NPIX (HH * WW)          // 8192
#define NH   8
#define HD   32
#define C3   (3 * CC)           // 768
#define KK   7

// ---------------------------------------------------------------------------
// Scratch (device globals; no allocation allowed)
// ---------------------------------------------------------------------------
__device__ __align__(16) float         g_q[NPIX * CC];          // q fp32
__device__ __align__(16) __half        g_kv[NPIX * 2 * CC];     // k|v fp16 (512/pix)
__device__ __align__(16) __half        g_atn[NPIX * CC];        // attention out fp16
__device__ __align__(16) __nv_bfloat16 g_xh[NPIX * CC];
__device__ __align__(16) __nv_bfloat16 g_xl[NPIX * CC];
__device__ __align__(16) __nv_bfloat16 g_wqkvT_h[C3 * CC];
__device__ __align__(16) __nv_bfloat16 g_wqkvT_l[C3 * CC];
__device__ __align__(16) __half        g_wprojT_h[CC * CC];     // fp16 hi
__device__ __align__(16) __half        g_wprojT_l[CC * CC];     // fp16 lo

// ---------------------------------------------------------------------------
// PTX helpers (baseline ISA: mma.sync / ldmatrix / cp.async)
// ---------------------------------------------------------------------------
__device__ __forceinline__ uint32_t smem_u32(const void* p) {
    uint32_t a;
    asm("{ .reg .u64 t; cvta.to.shared.u64 t, %1; cvt.u32.u64 %0, t; }"
        : "=r"(a) : "l"(p));
    return a;
}

__device__ __forceinline__ void cp_async16(uint32_t saddr, const void* gptr) {
    asm volatile("cp.async.cg.shared.global [%0], [%1], 16;"
                 :: "r"(saddr), "l"(gptr) : "memory");
}

__device__ __forceinline__ void ldsm_x4(uint32_t* r, uint32_t addr) {
    asm volatile("ldmatrix.sync.aligned.m8n8.x4.shared.b16 {%0,%1,%2,%3}, [%4];"
                 : "=r"(r[0]), "=r"(r[1]), "=r"(r[2]), "=r"(r[3]) : "r"(addr));
}

__device__ __forceinline__ void mma_16816(float* c, const uint32_t* a,
                                          const uint32_t* b) {
    asm volatile(
        "mma.sync.aligned.m16n8k16.row.col.f32.bf16.bf16.f32 "
        "{%0,%1,%2,%3}, {%4,%5,%6,%7}, {%8,%9}, {%0,%1,%2,%3};"
        : "+f"(c[0]), "+f"(c[1]), "+f"(c[2]), "+f"(c[3])
        : "r"(a[0]), "r"(a[1]), "r"(a[2]), "r"(a[3]), "r"(b[0]), "r"(b[1]));
}

__device__ __forceinline__ void mma_16816_f16(float* c, const uint32_t* a,
                                              const uint32_t* b) {
    asm volatile(
        "mma.sync.aligned.m16n8k16.row.col.f32.f16.f16.f32 "
        "{%0,%1,%2,%3}, {%4,%5,%6,%7}, {%8,%9}, {%0,%1,%2,%3};"
        : "+f"(c[0]), "+f"(c[1]), "+f"(c[2]), "+f"(c[3])
        : "r"(a[0]), "r"(a[1]), "r"(a[2]), "r"(a[3]), "r"(b[0]), "r"(b[1]));
}

// SW64 swizzle for 64B rows: chunk bits [4:5] ^= row-pair bits [7:8]
__device__ __forceinline__ uint32_t sw64(uint32_t off) {
    return off ^ ((off >> 3) & 0x30);
}

// ---------------------------------------------------------------------------
// Fused prep: split x (hi/lo bf16, float4-vectorized) + transpose/split weights
// (w_qkv -> bf16 hi/lo; w_proj -> fp16 hi/lo)
// ---------------------------------------------------------------------------
#define PREP_XB  (NPIX * CC / 1024)           // 2048 (4 elems/thread)
#define PREP_QB  (CC * C3 / 256)              // 768
#define PREP_PB  (CC * CC / 256)              // 256

__global__ void prep_all(const float* __restrict__ x,
                         const float* __restrict__ wq,
                         const float* __restrict__ wp,
                         __nv_bfloat16* __restrict__ xh, __nv_bfloat16* __restrict__ xl,
                         __nv_bfloat16* __restrict__ qh, __nv_bfloat16* __restrict__ ql,
                         __half* __restrict__ ph, __half* __restrict__ pl)
{
    const int b = blockIdx.x;
    if (b < PREP_XB) {
        const int i4 = (b * 256 + threadIdx.x) * 4;
        const float4 v = *(const float4*)&x[i4];
        __nv_bfloat16 h[4], l[4];
        const float vv[4] = {v.x, v.y, v.z, v.w};
#pragma unroll
        for (int j = 0; j < 4; j++) {
            h[j] = __float2bfloat16(vv[j]);
            l[j] = __float2bfloat16(vv[j] - __bfloat162float(h[j]));
        }
        *(uint2*)&xh[i4] = *(const uint2*)h;
        *(uint2*)&xl[i4] = *(const uint2*)l;
    } else if (b < PREP_XB + PREP_QB) {
        const int i = (b - PREP_XB) * 256 + threadIdx.x;   // over C3*CC
        const int n = i / CC, k = i % CC;
        const float v = wq[(size_t)k * C3 + n];
        const __nv_bfloat16 hi = __float2bfloat16(v);
        qh[i] = hi;                                        // i == n*CC + k
        ql[i] = __float2bfloat16(v - __bfloat162float(hi));
    } else {
        const int i = (b - PREP_XB - PREP_QB) * 256 + threadIdx.x;  // CC*CC
        const int n = i / CC, k = i % CC;
        const float v = wp[(size_t)k * CC + n];
        const __half hi = __float2half_rn(v);
        ph[i] = hi;
        pl[i] = __float2half_rn(v - __half2float(hi));
    }
}

// ---------------------------------------------------------------------------
// QKV GEMM: bf16 3-term (Ah@Bh + Ah@Bl + Al@Bh). CTA 128x64, 4 warps,
// warp tile 64x32. BKC=32, 64B rows + SW64, 2-stage cp.async, 3 CTA/SM.
// Epilogue: tiles bx < nq  -> fp32 into Cq  (width 256)
//           tiles bx >= nq -> fp16 into Ckv (width 512 halves; k|v packed)
// ---------------------------------------------------------------------------
#define BKC 32
#define AB_BYTES (128 * 64)                  // 8192 per A buffer
#define BB_BYTES (64 * 64)                   // 4096 per B buffer
#define STG_BYTES (2 * AB_BYTES + 2 * BB_BYTES)  // 24576
#define GT_SMEM (2 * STG_BYTES)              // 49152

__global__ __launch_bounds__(128, 3)
void gemm_mma(const __nv_bfloat16* __restrict__ Ah, const __nv_bfloat16* __restrict__ Al,
              const __nv_bfloat16* __restrict__ Bh, const __nv_bfloat16* __restrict__ Bl,
              const float* __restrict__ bias,
              float* __restrict__ Cq, __half* __restrict__ Ckv,
              int nq, int K)
{
    extern __shared__ char smem[];
    const uint32_t sb = smem_u32(smem);
    const int tid  = threadIdx.x;
    const int wid  = tid >> 5;
    const int lane = tid & 31;
    const int warpM = wid & 1;
    const int warpN = wid >> 1;

    const size_t aBase = (size_t)blockIdx.y * 128 * K;
    const size_t bBase = (size_t)blockIdx.x * 64 * K;
    const int nch = K / BKC;

    auto issue_chunk = [&](int c) {
        const uint32_t st = sb + (uint32_t)(c & 1) * STG_BYTES;
        const int k0 = c * BKC;
#pragma unroll
        for (int i = 0; i < 4; i++) {
            const int idx = i * 128 + tid;
            const int r = idx >> 2, u = idx & 3;
            const uint32_t so = sw64((uint32_t)r * 64 + (uint32_t)u * 16);
            const size_t ga = aBase + (size_t)r * K + k0 + u * 8;
            cp_async16(st + so, Ah + ga);
            cp_async16(st + AB_BYTES + so, Al + ga);
        }
#pragma unroll
        for (int i = 0; i < 2; i++) {
            const int idx = i * 128 + tid;
            const int r = idx >> 2, u = idx & 3;
            const uint32_t so = sw64((uint32_t)r * 64 + (uint32_t)u * 16);
            const size_t gb = bBase + (size_t)r * K + k0 + u * 8;
            cp_async16(st + 2 * AB_BYTES + so, Bh + gb);
            cp_async16(st + 2 * AB_BYTES + BB_BYTES + so, Bl + gb);
        }
        asm volatile("cp.async.commit_group;" ::: "memory");
    };

    float acc[4][4][4];
#pragma unroll
    for (int i = 0; i < 4; i++)
#pragma unroll
        for (int j = 0; j < 4; j++)
#pragma unroll
            for (int t = 0; t < 4; t++) acc[i][j][t] = 0.0f;

    const uint32_t arow  = (uint32_t)(warpM * 64 + (lane & 15));
    const uint32_t acolL = (uint32_t)((lane >> 4) * 16);
    const uint32_t brow  = (uint32_t)(warpN * 32 + (lane & 7) + ((lane >> 4) << 3));
    const uint32_t bcolL = (uint32_t)(((lane >> 3) & 1) * 16);

    issue_chunk(0);

    for (int c = 0; c < nch; c++) {
        if (c + 1 < nch) {
            issue_chunk(c + 1);
            asm volatile("cp.async.wait_group 1;" ::: "memory");
        } else {
            asm volatile("cp.async.wait_group 0;" ::: "memory");
        }
        __syncthreads();

        const uint32_t st  = sb + (uint32_t)(c & 1) * STG_BYTES;
        const uint32_t sA0 = st;
        const uint32_t sA1 = st + AB_BYTES;
        const uint32_t sB0 = st + 2 * AB_BYTES;
        const uint32_t sB1 = st + 2 * AB_BYTES + BB_BYTES;

#pragma unroll
        for (int ks = 0; ks < 2; ks++) {
            const uint32_t kb = (uint32_t)ks * 32;

            uint32_t ah[4][4], al[4][4];
#pragma unroll
            for (int ma = 0; ma < 4; ma++) {
                const uint32_t off = sw64((arow + ma * 16) * 64 + kb + acolL);
                ldsm_x4(ah[ma], sA0 + off);
                ldsm_x4(al[ma], sA1 + off);
            }

            uint32_t bh[4][2], bl[4][2];
#pragma unroll
            for (int g = 0; g < 2; g++) {
                const uint32_t off = sw64((brow + g * 16) * 64 + kb + bcolL);
                uint32_t t0[4], t1[4];
                ldsm_x4(t0, sB0 + off);
                ldsm_x4(t1, sB1 + off);
                bh[2 * g][0] = t0[0]; bh[2 * g][1] = t0[1];
                bh[2 * g + 1][0] = t0[2]; bh[2 * g + 1][1] = t0[3];
                bl[2 * g][0] = t1[0]; bl[2 * g][1] = t1[1];
                bl[2 * g + 1][0] = t1[2]; bl[2 * g + 1][1] = t1[3];
            }

#pragma unroll
            for (int ma = 0; ma < 4; ma++)
#pragma unroll
                for (int na = 0; na < 4; na++) {
                    mma_16816(acc[ma][na], ah[ma], bh[na]);
                    mma_16816(acc[ma][na], ah[ma], bl[na]);
                    mma_16816(acc[ma][na], al[ma], bh[na]);
                }
        }
        __syncthreads();
    }

    const int bx = blockIdx.x;
    const int row0 = blockIdx.y * 128 + warpM * 64 + (lane >> 2);
    const int lcol = warpN * 32 + (lane & 3) * 2;
#pragma unroll
    for (int na = 0; na < 4; na++) {
        const int wc = lcol + na * 8;
        const int gcol = bx * 64 + wc;
        const float2 b2 = *(const float2*)&bias[gcol];
        if (bx < nq) {
#pragma unroll
            for (int ma = 0; ma < 4; ma++) {
                const int r = row0 + ma * 16;
                float2 o0, o1;
                o0.x = acc[ma][na][0] + b2.x;
                o0.y = acc[ma][na][1] + b2.y;
                o1.x = acc[ma][na][2] + b2.x;
                o1.y = acc[ma][na][3] + b2.y;
                *(float2*)&Cq[(size_t)r * 256 + gcol]       = o0;
                *(float2*)&Cq[(size_t)(r + 8) * 256 + gcol] = o1;
            }
        } else {
            const int kvc = (bx - nq) * 64 + wc;
#pragma unroll
            for (int ma = 0; ma < 4; ma++) {
                const int r = row0 + ma * 16;
                __half2 o0 = __floats2half2_rn(acc[ma][na][0] + b2.x,
                                               acc[ma][na][1] + b2.y);
                __half2 o1 = __floats2half2_rn(acc[ma][na][2] + b2.x,
                                               acc[ma][na][3] + b2.y);
                *(__half2*)&Ckv[(size_t)r * 512 + kvc]       = o0;
                *(__half2*)&Ckv[(size_t)(r + 8) * 512 + kvc] = o1;
            }
        }
    }
}

// ---------------------------------------------------------------------------
// PROJ GEMM: fp16 2-term (A @ Bh + A @ Bl), A = attention out fp16 (single).
// CTA 128x64, warp 64x32, BKC=32, SW64. Stage 16KB -> 32KB total.
// N fixed to 256. Output fp32 + bias (final result).
// ---------------------------------------------------------------------------
#define PAB (128 * 64)                        // 8192: A fp16 tile
#define PBB (64 * 64)                         // 4096: B tile per buffer
#define PSTG (PAB + 2 * PBB)                  // 16384
#define GP_SMEM (2 * PSTG)                    // 32768

__global__ __launch_bounds__(128, 3)
void gemm_proj(const __half* __restrict__ A,
               const __half* __restrict__ Bh, const __half* __restrict__ Bl,
               const float* __restrict__ bias, float* __restrict__ C, int K)
{
    extern __shared__ char smem[];
    const uint32_t sb = smem_u32(smem);
    const int tid  = threadIdx.x;
    const int wid  = tid >> 5;
    const int lane = tid & 31;
    const int warpM = wid & 1;
    const int warpN = wid >> 1;

    const size_t aBase = (size_t)blockIdx.y * 128 * K;
    const size_t bBase = (size_t)blockIdx.x * 64 * K;
    const int nch = K / BKC;

    auto issue_chunk = [&](int c) {
        const uint32_t st = sb + (uint32_t)(c & 1) * PSTG;
        const int k0 = c * BKC;
        // A: 128 rows x 4 units = 512 transfers -> 4 iters
#pragma unroll
        for (int i = 0; i < 4; i++) {
            const int idx = i * 128 + tid;
            const int r = idx >> 2, u = idx & 3;
            const uint32_t so = sw64((uint32_t)r * 64 + (uint32_t)u * 16);
            cp_async16(st + so, A + aBase + (size_t)r * K + k0 + u * 8);
        }
        // B hi/lo: 64 rows x 4 units = 256 -> 2 iters each
#pragma unroll
        for (int i = 0; i < 2; i++) {
            const int idx = i * 128 + tid;
            const int r = idx >> 2, u = idx & 3;
            const uint32_t so = sw64((uint32_t)r * 64 + (uint32_t)u * 16);
            const size_t gb = bBase + (size_t)r * K + k0 + u * 8;
            cp_async16(st + PAB + so, Bh + gb);
            cp_async16(st + PAB + PBB + so, Bl + gb);
        }
        asm volatile("cp.async.commit_group;" ::: "memory");
    };

    float acc[4][4][4];
#pragma unroll
    for (int i = 0; i < 4; i++)
#pragma unroll
        for (int j = 0; j < 4; j++)
#pragma unroll
            for (int t = 0; t < 4; t++) acc[i][j][t] = 0.0f;

    const uint32_t arow  = (uint32_t)(warpM * 64 + (lane & 15));
    const uint32_t acolL = (uint32_t)((lane >> 4) * 16);
    const uint32_t brow  = (uint32_t)(warpN * 32 + (lane & 7) + ((lane >> 4) << 3));
    const uint32_t bcolL = (uint32_t)(((lane >> 3) & 1) * 16);

    issue_chunk(0);

    for (int c = 0; c < nch; c++) {
        if (c + 1 < nch) {
            issue_chunk(c + 1);
            asm volatile("cp.async.wait_group 1;" ::: "memory");
        } else {
            asm volatile("cp.async.wait_group 0;" ::: "memory");
        }
        __syncthreads();

        const uint32_t st  = sb + (uint32_t)(c & 1) * PSTG;
        const uint32_t sA  = st;
        const uint32_t sB0 = st + PAB;
        const uint32_t sB1 = st + PAB + PBB;

#pragma unroll
        for (int ks = 0; ks < 2; ks++) {
            const uint32_t kb = (uint32_t)ks * 32;

            uint32_t a[4][4];
#pragma unroll
            for (int ma = 0; ma < 4; ma++) {
                const uint32_t off = sw64((arow + ma * 16) * 64 + kb + acolL);
                ldsm_x4(a[ma], sA + off);
            }

            uint32_t bh[4][2], bl[4][2];
#pragma unroll
            for (int g = 0; g < 2; g++) {
                const uint32_t off = sw64((brow + g * 16) * 64 + kb + bcolL);
                uint32_t t0[4], t1[4];
                ldsm_x4(t0, sB0 + off);
                ldsm_x4(t1, sB1 + off);
                bh[2 * g][0] = t0[0]; bh[2 * g][1] = t0[1];
                bh[2 * g + 1][0] = t0[2]; bh[2 * g + 1][1] = t0[3];
                bl[2 * g][0] = t1[0]; bl[2 * g][1] = t1[1];
                bl[2 * g + 1][0] = t1[2]; bl[2 * g + 1][1] = t1[3];
            }

#pragma unroll
            for (int ma = 0; ma < 4; ma++)
#pragma unroll
                for (int na = 0; na < 4; na++) {
                    mma_16816_f16(acc[ma][na], a[ma], bh[na]);
                    mma_16816_f16(acc[ma][na], a[ma], bl[na]);
                }
        }
        __syncthreads();
    }

    const int row0 = blockIdx.y * 128 + warpM * 64 + (lane >> 2);
    const int col0 = blockIdx.x * 64 + warpN * 32 + (lane & 3) * 2;
#pragma unroll
    for (int na = 0; na < 4; na++) {
        const int cc = col0 + na * 8;
        const float2 b2 = *(const float2*)&bias[cc];
#pragma unroll
        for (int ma = 0; ma < 4; ma++) {
            const int r = row0 + ma * 16;
            float2 o0, o1;
            o0.x = acc[ma][na][0] + b2.x;
            o0.y = acc[ma][na][1] + b2.y;
            o1.x = acc[ma][na][2] + b2.x;
            o1.y = acc[ma][na][3] + b2.y;
            *(float2*)&C[(size_t)r * 256 + cc]       = o0;
            *(float2*)&C[(size_t)(r + 8) * 256 + cc] = o1;
        }
    }
}

// ---------------------------------------------------------------------------
// 2D neighborhood attention (7x7): one pixel per thread, single fused pass.
// (R13 config: 16x16 tile, 80B pixel stride, conflict-free, bounded-score exp)
// Output: single fp16 buffer (proj GEMM A operand).
// ---------------------------------------------------------------------------
#define ATS   16
#define AWIN  22
#define APS   80
#define AKV   (AWIN * AWIN * APS)             // 38720 per buffer
#define AT_SMEM (2 * AKV)                     // 77440

__global__ __launch_bounds__(256, 2)
void na_attn(const float* __restrict__ qbuf, const __half* __restrict__ kvbuf,
             __half* __restrict__ outp)
{
    extern __shared__ char smn[];
    char* sK = smn;
    char* sV = smn + AKV;

    const int c0   = blockIdx.x * ATS;
    const int r0   = blockIdx.y * ATS;
    const int head = blockIdx.z;

    const int rlo = max(r0 - 3, 0);
    const int rhi = min(r0 + ATS + 2, HH - 1);
    const int nr  = rhi - rlo + 1;
    const int clo = max(c0 - 3, 0);
    const int chi = min(c0 + ATS + 2, WW - 1);
    const int nc  = chi - clo + 1;
    const int npx = nr * nc;

    const int tid = threadIdx.x;

    for (int t = tid; t < npx * 4; t += 256) {
        const int p = t >> 2, u = t & 3;
        const int gy = rlo + p / nc;
        const int gx = clo + p % nc;
        const __half* base = kvbuf + (size_t)(gy * WW + gx) * 512 + head * HD;
        *(uint4*)(sK + p * APS + u * 16) = *(const uint4*)(base + u * 8);
        *(uint4*)(sV + p * APS + u * 16) = *(const uint4*)(base + 256 + u * 8);
    }
    __syncthreads();

    const int ly = tid >> 4, lx = tid & 15;
    const int gy = r0 + ly, gx = c0 + lx;
    const size_t pix = (size_t)(gy * WW + gx);
    const float scale = 0.17677669529663687f;

    __half2 qh[16];
    {
        const float4* qp = (const float4*)&qbuf[pix * CC + head * HD];
#pragma unroll
        for (int i = 0; i < 8; i++) {
            const float4 v = qp[i];
            qh[2 * i + 0] = __floats2half2_rn(v.x * scale, v.y * scale);
            qh[2 * i + 1] = __floats2half2_rn(v.z * scale, v.w * scale);
        }
    }

    const int sy = min(max(gy - 3, 0), HH - KK) - rlo;
    const int sx = min(max(gx - 3, 0), WW - KK) - clo;
    const int pbase = sy * nc + sx;

    float acc[32];
#pragma unroll
    for (int i = 0; i < 32; i++) acc[i] = 0.0f;
    float l = 0.0f;

    const __half2 z2 = __float2half2_rn(0.0f);

#pragma unroll 1
    for (int p = 0; p < KK; p++) {
        const char* krow = sK + (size_t)(pbase + p * nc) * APS;
        const char* vrow = sV + (size_t)(pbase + p * nc) * APS;
#pragma unroll
        for (int qq = 0; qq < KK; qq++) {
            const uint4* kp = (const uint4*)(krow + qq * APS);
            __half2 s2a = z2, s2b = z2;
#pragma unroll
            for (int i = 0; i < 4; i++) {
                const uint4 u = kp[i];
                s2a = __hfma2(qh[4 * i + 0], *(const __half2*)&u.x, s2a);
                s2b = __hfma2(qh[4 * i + 1], *(const __half2*)&u.y, s2b);
                s2a = __hfma2(qh[4 * i + 2], *(const __half2*)&u.z, s2a);
                s2b = __hfma2(qh[4 * i + 3], *(const __half2*)&u.w, s2b);
            }
            const float2 fa = __half22float2(s2a);
            const float2 fb = __half22float2(s2b);
            const float s = (fa.x + fa.y) + (fb.x + fb.y);

            const float e = __expf(s);
            l += e;

            const uint4* vp = (const uint4*)(vrow + qq * APS);
#pragma unroll
            for (int i = 0; i < 4; i++) {
                const uint4 u = vp[i];
                const float2 f0 = __half22float2(*(const __half2*)&u.x);
                const float2 f1 = __half22float2(*(const __half2*)&u.y);
                const float2 f2 = __half22float2(*(const __half2*)&u.z);
                const float2 f3 = __half22float2(*(const __half2*)&u.w);
                acc[8 * i + 0] = fmaf(e, f0.x, acc[8 * i + 0]);
                acc[8 * i + 1] = fmaf(e, f0.y, acc[8 * i + 1]);
                acc[8 * i + 2] = fmaf(e, f1.x, acc[8 * i + 2]);
                acc[8 * i + 3] = fmaf(e, f1.y, acc[8 * i + 3]);
                acc[8 * i + 4] = fmaf(e, f2.x, acc[8 * i + 4]);
                acc[8 * i + 5] = fmaf(e, f2.y, acc[8 * i + 5]);
                acc[8 * i + 6] = fmaf(e, f3.x, acc[8 * i + 6]);
                acc[8 * i + 7] = fmaf(e, f3.y, acc[8 * i + 7]);
            }
        }
    }

    // ---- output: single fp16 buffer ----
    const float inv = 1.0f / l;
    const size_t idx = pix * CC + head * HD;
#pragma unroll
    for (int i = 0; i < 8; i++) {
        __half2 hp[2];
        hp[0] = __floats2half2_rn(acc[4 * i + 0] * inv, acc[4 * i + 1] * inv);
        hp[1] = __floats2half2_rn(acc[4 * i + 2] * inv, acc[4 * i + 3] * inv);
        *(uint2*)&outp[idx + 4 * i] = *(const uint2*)hp;
    }
}

// ---------------------------------------------------------------------------
// kernel_launch
// ---------------------------------------------------------------------------
extern "C" void kernel_launch(void* const* d_in, const int* in_sizes, int n_in,
                              void* d_out, int out_size)
{
    const float* x      = (const float*)d_in[0];
    const float* w_qkv  = (const float*)d_in[1];
    const float* b_qkv  = (const float*)d_in[2];
    const float* w_proj = (const float*)d_in[3];
    const float* b_proj = (const float*)d_in[4];
    float* out = (float*)d_out;

    float *qb;
    __half *kvb, *atn, *wph, *wpl;
    __nv_bfloat16 *xh, *xl, *wqh, *wql;
    cudaGetSymbolAddress((void**)&qb,  g_q);
    cudaGetSymbolAddress((void**)&kvb, g_kv);
    cudaGetSymbolAddress((void**)&atn, g_atn);
    cudaGetSymbolAddress((void**)&xh,  g_xh);
    cudaGetSymbolAddress((void**)&xl,  g_xl);
    cudaGetSymbolAddress((void**)&wqh, g_wqkvT_h);
    cudaGetSymbolAddress((void**)&wql, g_wqkvT_l);
    cudaGetSymbolAddress((void**)&wph, g_wprojT_h);
    cudaGetSymbolAddress((void**)&wpl, g_wprojT_l);

    cudaFuncSetAttribute(gemm_mma, cudaFuncAttributeMaxDynamicSharedMemorySize,
                         GT_SMEM);
    cudaFuncSetAttribute(gemm_proj, cudaFuncAttributeMaxDynamicSharedMemorySize,
                         GP_SMEM);
    cudaFuncSetAttribute(na_attn, cudaFuncAttributeMaxDynamicSharedMemorySize,
                         AT_SMEM);

    // 0) Fused prep
    prep_all<<<PREP_XB + PREP_QB + PREP_PB, 256>>>(x, w_qkv, w_proj,
                                                   xh, xl, wqh, wql, wph, wpl);

    // 1) QKV projection (bf16 3-term): [8192,256] @ [256,768] + b
    //    64-col tiles 0-3 -> q fp32; tiles 4-11 -> k|v fp16
    {
        dim3 grid(C3 / 64, NPIX / 128);
        gemm_mma<<<grid, 128, GT_SMEM>>>(xh, xl, wqh, wql, b_qkv,
                                         qb, kvb, /*nq=*/4, CC);
    }

    // 2) Neighborhood attention -> fp16 out
    {
        dim3 grid(WW / ATS, HH / ATS, NH);
        na_attn<<<grid, 256, AT_SMEM>>>(qb, kvb, atn);
    }

    // 3) Output projection (fp16 2-term): [8192,256] @ [256,256] + b
    {
        dim3 grid(CC / 64, NPIX / 128);
        gemm_proj<<<grid, 128, GP_SMEM>>>(atn, wph, wpl, b_proj, out, CC);
    }
}